// round 1
// baseline (speedup 1.0000x reference)
#include <cuda_runtime.h>
#include <cstdint>

#define NUM_T 15

// y = b + sum_i alpha_i * (x >= th_i)
// Pure elementwise, HBM-bound. float4 vectorization, 4 float4 per thread
// (front-batched LDG.128s for MLP), thresholds/alphas in registers.
__global__ __launch_bounds__(256)
void kq_kernel(const float4* __restrict__ x,
               float4* __restrict__ y,
               const float* __restrict__ th,
               const float* __restrict__ al,
               const float* __restrict__ bp,
               long long n4)
{
    // Hoist quantizer params into registers (broadcast L1 hits, amortized
    // over 16 output elements per thread).
    float t[NUM_T], a[NUM_T];
#pragma unroll
    for (int i = 0; i < NUM_T; i++) {
        t[i] = __ldg(th + i);
        a[i] = __ldg(al + i);
    }
    const float b = __ldg(bp);

    const long long base = ((long long)blockIdx.x * blockDim.x + threadIdx.x) * 4;
    const long long gstride = (long long)gridDim.x * blockDim.x; // elements between the 4 per-thread float4s? no:
    // We lay out the 4 float4s per thread strided by total thread count so
    // loads within a warp stay fully coalesced at every step.
    (void)gstride;

    const long long nthreads = (long long)gridDim.x * blockDim.x;
    const long long tid = (long long)blockIdx.x * blockDim.x + threadIdx.x;

    // Each thread handles 4 float4s at tid, tid+nthreads, tid+2*nthreads, tid+3*nthreads.
    float4 v[4];
    long long idx[4];
#pragma unroll
    for (int k = 0; k < 4; k++) idx[k] = tid + (long long)k * nthreads;

    bool inb[4];
#pragma unroll
    for (int k = 0; k < 4; k++) inb[k] = (idx[k] < n4);

    // Front-batched loads (MLP = 4)
#pragma unroll
    for (int k = 0; k < 4; k++) {
        if (inb[k]) v[k] = x[idx[k]];
    }

#pragma unroll
    for (int k = 0; k < 4; k++) {
        if (!inb[k]) continue;
        float rx = b, ry = b, rz = b, rw = b;
#pragma unroll
        for (int i = 0; i < NUM_T; i++) {
            rx += (v[k].x >= t[i]) ? a[i] : 0.0f;
            ry += (v[k].y >= t[i]) ? a[i] : 0.0f;
            rz += (v[k].z >= t[i]) ? a[i] : 0.0f;
            rw += (v[k].w >= t[i]) ? a[i] : 0.0f;
        }
        y[idx[k]] = make_float4(rx, ry, rz, rw);
    }

    (void)base;
}

// Tail kernel for non-multiple-of-4 element counts (not needed for this
// shape, but keeps the launcher shape-robust).
__global__ void kq_tail(const float* __restrict__ x,
                        float* __restrict__ y,
                        const float* __restrict__ th,
                        const float* __restrict__ al,
                        const float* __restrict__ bp,
                        long long start, long long n)
{
    long long i = start + blockIdx.x * blockDim.x + threadIdx.x;
    if (i >= n) return;
    float v = x[i];
    float r = __ldg(bp);
#pragma unroll
    for (int k = 0; k < NUM_T; k++)
        r += (v >= __ldg(th + k)) ? __ldg(al + k) : 0.0f;
    y[i] = r;
}

extern "C" void kernel_launch(void* const* d_in, const int* in_sizes, int n_in,
                              void* d_out, int out_size)
{
    // Input order per setup_inputs: x, T, thresholds, alphas, b
    const float* x  = (const float*)d_in[0];
    // d_in[1] = T (backward-only, unused in forward)
    const float* th = (const float*)d_in[2];
    const float* al = (const float*)d_in[3];
    const float* bp = (const float*)d_in[4];
    float* y = (float*)d_out;

    const long long n = (long long)in_sizes[0];
    const long long n4 = n / 4;

    // 4 float4s per thread, 256 threads/block
    const int threads = 256;
    const long long work_per_block = (long long)threads * 4;
    long long blocks = (n4 + work_per_block - 1) / work_per_block;
    if (blocks < 1) blocks = 1;

    kq_kernel<<<(unsigned)blocks, threads>>>(
        (const float4*)x, (float4*)y, th, al, bp, n4);

    const long long rem_start = n4 * 4;
    if (rem_start < n) {
        long long rem = n - rem_start;
        int tb = (int)((rem + 255) / 256);
        kq_tail<<<tb, 256>>>(x, y, th, al, bp, rem_start, n);
    }
}

// round 2
// speedup vs baseline: 1.5898x; 1.5898x over previous
#include <cuda_runtime.h>
#include <cstdint>

#define NUM_T 15

// y = b + sum_i alpha_i * step(x - th_i)
// Key change vs R1: compare emitted as FSET (set.ge.f32.f32 -> 1.0f/0.0f,
// ALU pipe) fused with FFMA (fma pipe) instead of FSETP+FSEL+FADD (2 ALU ops).
// Halves ALU-pipe pressure, which was the measured bottleneck (86.4%).

__device__ __forceinline__ float ge_mask(float v, float t) {
    float m;
    asm("set.ge.f32.f32 %0, %1, %2;" : "=f"(m) : "f"(v), "f"(t));
    return m;
}

// Full-tile kernel: grid exactly covers n4 float4s, no bounds checks.
__global__ __launch_bounds__(256)
void kq_kernel_full(const float4* __restrict__ x,
                    float4* __restrict__ y,
                    const float* __restrict__ th,
                    const float* __restrict__ al,
                    const float* __restrict__ bp)
{
    float t[NUM_T], a[NUM_T];
#pragma unroll
    for (int i = 0; i < NUM_T; i++) {
        t[i] = __ldg(th + i);
        a[i] = __ldg(al + i);
    }
    const float b = __ldg(bp);

    const unsigned nthreads = gridDim.x * blockDim.x;
    const unsigned tid = blockIdx.x * blockDim.x + threadIdx.x;

    // 4 float4s per thread, strided by total thread count (coalesced),
    // front-batched loads for MLP=4.
    float4 v0 = x[tid];
    float4 v1 = x[tid + nthreads];
    float4 v2 = x[tid + 2u * nthreads];
    float4 v3 = x[tid + 3u * nthreads];

    float4 r0 = make_float4(b, b, b, b);
    float4 r1 = r0, r2 = r0, r3 = r0;

#pragma unroll
    for (int i = 0; i < NUM_T; i++) {
        r0.x = fmaf(ge_mask(v0.x, t[i]), a[i], r0.x);
        r0.y = fmaf(ge_mask(v0.y, t[i]), a[i], r0.y);
        r0.z = fmaf(ge_mask(v0.z, t[i]), a[i], r0.z);
        r0.w = fmaf(ge_mask(v0.w, t[i]), a[i], r0.w);
        r1.x = fmaf(ge_mask(v1.x, t[i]), a[i], r1.x);
        r1.y = fmaf(ge_mask(v1.y, t[i]), a[i], r1.y);
        r1.z = fmaf(ge_mask(v1.z, t[i]), a[i], r1.z);
        r1.w = fmaf(ge_mask(v1.w, t[i]), a[i], r1.w);
        r2.x = fmaf(ge_mask(v2.x, t[i]), a[i], r2.x);
        r2.y = fmaf(ge_mask(v2.y, t[i]), a[i], r2.y);
        r2.z = fmaf(ge_mask(v2.z, t[i]), a[i], r2.z);
        r2.w = fmaf(ge_mask(v2.w, t[i]), a[i], r2.w);
        r3.x = fmaf(ge_mask(v3.x, t[i]), a[i], r3.x);
        r3.y = fmaf(ge_mask(v3.y, t[i]), a[i], r3.y);
        r3.z = fmaf(ge_mask(v3.z, t[i]), a[i], r3.z);
        r3.w = fmaf(ge_mask(v3.w, t[i]), a[i], r3.w);
    }

    y[tid] = r0;
    y[tid + nthreads] = r1;
    y[tid + 2u * nthreads] = r2;
    y[tid + 3u * nthreads] = r3;
}

// Generic fallback (bounds-checked, scalar) for any residual / non-tiling shape.
__global__ void kq_tail(const float* __restrict__ x,
                        float* __restrict__ y,
                        const float* __restrict__ th,
                        const float* __restrict__ al,
                        const float* __restrict__ bp,
                        long long start, long long n)
{
    long long i = start + (long long)blockIdx.x * blockDim.x + threadIdx.x;
    if (i >= n) return;
    float v = x[i];
    float r = __ldg(bp);
#pragma unroll
    for (int k = 0; k < NUM_T; k++)
        r = fmaf(ge_mask(v, __ldg(th + k)), __ldg(al + k), r);
    y[i] = r;
}

extern "C" void kernel_launch(void* const* d_in, const int* in_sizes, int n_in,
                              void* d_out, int out_size)
{
    // Input order per setup_inputs: x, T, thresholds, alphas, b
    const float* x  = (const float*)d_in[0];
    // d_in[1] = T (backward-only, unused in forward)
    const float* th = (const float*)d_in[2];
    const float* al = (const float*)d_in[3];
    const float* bp = (const float*)d_in[4];
    float* y = (float*)d_out;

    const long long n = (long long)in_sizes[0];
    const int threads = 256;
    const long long per_block = (long long)threads * 4;  // float4s per block
    const long long n4 = n / 4;

    const long long full_blocks = n4 / per_block;
    const long long covered = full_blocks * per_block * 4;  // elements covered

    if (full_blocks > 0) {
        kq_kernel_full<<<(unsigned)full_blocks, threads>>>(
            (const float4*)x, (float4*)y, th, al, bp);
    }
    if (covered < n) {
        long long rem = n - covered;
        int tb = (int)((rem + 255) / 256);
        kq_tail<<<tb, 256>>>(x, y, th, al, bp, covered, n);
    }
}

// round 3
// speedup vs baseline: 1.5905x; 1.0004x over previous
#include <cuda_runtime.h>
#include <cstdint>

#define NUM_T 15

// y = b + sum_i alpha_i * step(x - th_i)
// R3 change: per-threshold work is FSETP + predicated FADD (forced via
// inline PTX @p add.f32). ptxas lowers C++ ternaries to FSETP+FSEL+FADD
// (30 ALU-pipe ops/elem, measured co-binding with DRAM); explicit
// predication gives 15 ALU + 15 FMA ops/elem, below the HBM floor.

__device__ __forceinline__ void step_add(float& r, float v, float t, float a) {
    asm("{\n\t"
        ".reg .pred p;\n\t"
        "setp.ge.f32 p, %1, %2;\n\t"
        "@p add.f32 %0, %0, %3;\n\t"
        "}"
        : "+f"(r) : "f"(v), "f"(t), "f"(a));
}

// Full-tile kernel: grid exactly covers n4 float4s, no bounds checks.
__global__ __launch_bounds__(256)
void kq_kernel_full(const float4* __restrict__ x,
                    float4* __restrict__ y,
                    const float* __restrict__ th,
                    const float* __restrict__ al,
                    const float* __restrict__ bp)
{
    float t[NUM_T], a[NUM_T];
#pragma unroll
    for (int i = 0; i < NUM_T; i++) {
        t[i] = __ldg(th + i);
        a[i] = __ldg(al + i);
    }
    const float b = __ldg(bp);

    const unsigned nthreads = gridDim.x * blockDim.x;
    const unsigned tid = blockIdx.x * blockDim.x + threadIdx.x;

    // 4 float4s per thread, strided by total thread count (coalesced),
    // front-batched loads for MLP=4.
    float4 v0 = x[tid];
    float4 v1 = x[tid + nthreads];
    float4 v2 = x[tid + 2u * nthreads];
    float4 v3 = x[tid + 3u * nthreads];

    float4 r0 = make_float4(b, b, b, b);
    float4 r1 = r0, r2 = r0, r3 = r0;

#pragma unroll
    for (int i = 0; i < NUM_T; i++) {
        step_add(r0.x, v0.x, t[i], a[i]);
        step_add(r0.y, v0.y, t[i], a[i]);
        step_add(r0.z, v0.z, t[i], a[i]);
        step_add(r0.w, v0.w, t[i], a[i]);
        step_add(r1.x, v1.x, t[i], a[i]);
        step_add(r1.y, v1.y, t[i], a[i]);
        step_add(r1.z, v1.z, t[i], a[i]);
        step_add(r1.w, v1.w, t[i], a[i]);
        step_add(r2.x, v2.x, t[i], a[i]);
        step_add(r2.y, v2.y, t[i], a[i]);
        step_add(r2.z, v2.z, t[i], a[i]);
        step_add(r2.w, v2.w, t[i], a[i]);
        step_add(r3.x, v3.x, t[i], a[i]);
        step_add(r3.y, v3.y, t[i], a[i]);
        step_add(r3.z, v3.z, t[i], a[i]);
        step_add(r3.w, v3.w, t[i], a[i]);
    }

    y[tid] = r0;
    y[tid + nthreads] = r1;
    y[tid + 2u * nthreads] = r2;
    y[tid + 3u * nthreads] = r3;
}

// Generic fallback (bounds-checked, scalar) for any residual / non-tiling shape.
__global__ void kq_tail(const float* __restrict__ x,
                        float* __restrict__ y,
                        const float* __restrict__ th,
                        const float* __restrict__ al,
                        const float* __restrict__ bp,
                        long long start, long long n)
{
    long long i = start + (long long)blockIdx.x * blockDim.x + threadIdx.x;
    if (i >= n) return;
    float v = x[i];
    float r = __ldg(bp);
#pragma unroll
    for (int k = 0; k < NUM_T; k++)
        step_add(r, v, __ldg(th + k), __ldg(al + k));
    y[i] = r;
}

extern "C" void kernel_launch(void* const* d_in, const int* in_sizes, int n_in,
                              void* d_out, int out_size)
{
    // Input order per setup_inputs: x, T, thresholds, alphas, b
    const float* x  = (const float*)d_in[0];
    // d_in[1] = T (backward-only, unused in forward)
    const float* th = (const float*)d_in[2];
    const float* al = (const float*)d_in[3];
    const float* bp = (const float*)d_in[4];
    float* y = (float*)d_out;

    const long long n = (long long)in_sizes[0];
    const int threads = 256;
    const long long per_block = (long long)threads * 4;  // float4s per block
    const long long n4 = n / 4;

    const long long full_blocks = n4 / per_block;
    const long long covered = full_blocks * per_block * 4;  // elements covered

    if (full_blocks > 0) {
        kq_kernel_full<<<(unsigned)full_blocks, threads>>>(
            (const float4*)x, (float4*)y, th, al, bp);
    }
    if (covered < n) {
        long long rem = n - covered;
        int tb = (int)((rem + 255) / 256);
        kq_tail<<<tb, 256>>>(x, y, th, al, bp, covered, n);
    }
}